// round 2
// baseline (speedup 1.0000x reference)
#include <cuda_runtime.h>
#include <cstdint>

#define N_NODES 100000
#define N_EDGES 1600000
#define D 128
#define L 3

// ---------------- scratch (device globals; no allocation allowed) ----------
__device__ __align__(16) float g_agg [N_NODES * D];   // neighbor-sum accumulator
__device__ __align__(16) float g_buf0[N_NODES * D];   // ping-pong feature buffers
__device__ __align__(16) float g_buf1[N_NODES * D];
__device__ float    g_inv [N_NODES];       // 1 / max(count,1)
__device__ int      g_cnt [N_NODES];
__device__ unsigned g_minbuf[D];           // monotone-uint min accumulator

// monotone mapping: order-preserving float -> uint
__device__ __forceinline__ unsigned f2mono(float f) {
    unsigned u = __float_as_uint(f);
    return (u & 0x80000000u) ? ~u : (u | 0x80000000u);
}
__device__ __forceinline__ float mono2f(unsigned m) {
    return (m & 0x80000000u) ? __uint_as_float(m ^ 0x80000000u)
                             : __uint_as_float(~m);
}

// ---------------- init: zero counts + reset min buffer ---------------------
__global__ void k_init(void) {
    int i = blockIdx.x * blockDim.x + threadIdx.x;
    if (i < N_NODES) g_cnt[i] = 0;
    if (i < D)       g_minbuf[i] = 0xFFFFFFFFu;
}

// ---------------- degree histogram -----------------------------------------
__global__ void k_count(const int* __restrict__ ei) {
    int e = blockIdx.x * blockDim.x + threadIdx.x;
    if (e >= N_EDGES) return;
    int dst = ei[N_EDGES + e];
    atomicAdd(&g_cnt[dst], 1);
}

__global__ void k_inv(void) {
    int i = blockIdx.x * blockDim.x + threadIdx.x;
    if (i >= N_NODES) return;
    g_inv[i] = 1.0f / fmaxf((float)g_cnt[i], 1.0f);
}

// ---------------- zero the aggregation buffer (float4) ---------------------
__global__ void k_zero_agg(void) {
    int i = blockIdx.x * blockDim.x + threadIdx.x;
    if (i < N_NODES * D / 4) {
        float4 z = make_float4(0.f, 0.f, 0.f, 0.f);
        ((float4*)g_agg)[i] = z;
    }
}

// ---------------- edge scatter: one warp per edge ---------------------------
// warp loads x[src] row (32 x float4) and red.add.v4 into agg[dst]
__global__ void k_scatter(const int* __restrict__ ei,
                          const float* __restrict__ xcur) {
    long long gtid = (long long)blockIdx.x * blockDim.x + threadIdx.x;
    int e    = (int)(gtid >> 5);
    int lane = threadIdx.x & 31;
    if (e >= N_EDGES) return;

    int s = 0, d = 0;
    if (lane == 0) { s = ei[e]; d = ei[N_EDGES + e]; }
    s = __shfl_sync(0xFFFFFFFFu, s, 0);
    d = __shfl_sync(0xFFFFFFFFu, d, 0);
    int src = s, dst = d;

    float4 v = ((const float4*)(xcur + (long long)src * D))[lane];
    float* p = g_agg + (long long)dst * D + lane * 4;
    asm volatile("red.global.add.v4.f32 [%0], {%1,%2,%3,%4};"
                 :: "l"(p), "f"(v.x), "f"(v.y), "f"(v.z), "f"(v.w)
                 : "memory");
}

// ---------------- fused SAGE layer GEMM -------------------------------------
// out[n,j] = sum_k mean[n,k]*Wl[j,k] + sum_k x[n,k]*Wr[j,k] + bl[j]
// Treated as A[N,256] @ B[128,256]^T with A = [agg*inv | x], B = [Wl | Wr].
// BM=64 nodes, BN=128 cols, BK=32, 256 threads, thread tile 4x8.
#define BM 64
#define BN 128
#define BK 32

template<int RELU>
__global__ void __launch_bounds__(256)
k_gemm(const float* __restrict__ xcur,
       const float* __restrict__ Wl,
       const float* __restrict__ bl,
       const float* __restrict__ Wr,
       float* __restrict__ xnext) {
    __shared__ float As[BM][BK];        // [node][k]
    __shared__ float Bs[BK][BN + 4];    // [k][col], padded

    int tid   = threadIdx.x;
    int tcol  = tid & 15;               // 16 col-groups of 8
    int trow  = tid >> 4;               // 16 node-groups of 4
    int j0    = tcol * 8;
    int n0    = trow * 4;
    int node0 = blockIdx.x * BM;

    float acc[4][8];
#pragma unroll
    for (int i = 0; i < 4; i++)
#pragma unroll
        for (int c = 0; c < 8; c++) acc[i][c] = 0.f;

    for (int kc = 0; kc < 8; kc++) {    // 8 chunks of 32 over K=256
        bool meanRegion = (kc < 4);
        int  kb = meanRegion ? kc * 32 : (kc - 4) * 32;

        // --- load A tile: 64 nodes x 32 k = 512 float4, 2 per thread
#pragma unroll
        for (int it = 0; it < 2; it++) {
            int idx = tid + it * 256;
            int nl  = idx >> 3;          // 0..63
            int kk  = (idx & 7) * 4;     // 0..28
            int n   = node0 + nl;
            if (n >= N_NODES) n = N_NODES - 1;
            float4 v;
            if (meanRegion) {
                v = *(const float4*)(g_agg + (long long)n * D + kb + kk);
                float s = g_inv[n];
                v.x *= s; v.y *= s; v.z *= s; v.w *= s;
            } else {
                v = *(const float4*)(xcur + (long long)n * D + kb + kk);
            }
            *(float4*)&As[nl][kk] = v;
        }
        // --- load B tile (transposed): 128 cols x 32 k = 1024 float4, 4/thread
        const float* Wsrc = meanRegion ? Wl : Wr;
#pragma unroll
        for (int it = 0; it < 4; it++) {
            int idx = tid + it * 256;
            int j   = idx >> 3;          // 0..127
            int kk  = (idx & 7) * 4;
            float4 v = *(const float4*)(Wsrc + j * D + kb + kk);
            Bs[kk + 0][j] = v.x;
            Bs[kk + 1][j] = v.y;
            Bs[kk + 2][j] = v.z;
            Bs[kk + 3][j] = v.w;
        }
        __syncthreads();

#pragma unroll
        for (int kk = 0; kk < BK; kk++) {
            float4 b0 = *(float4*)&Bs[kk][j0];
            float4 b1 = *(float4*)&Bs[kk][j0 + 4];
            float a[4];
#pragma unroll
            for (int i = 0; i < 4; i++) a[i] = As[n0 + i][kk];
#pragma unroll
            for (int i = 0; i < 4; i++) {
                acc[i][0] += a[i] * b0.x;
                acc[i][1] += a[i] * b0.y;
                acc[i][2] += a[i] * b0.z;
                acc[i][3] += a[i] * b0.w;
                acc[i][4] += a[i] * b1.x;
                acc[i][5] += a[i] * b1.y;
                acc[i][6] += a[i] * b1.z;
                acc[i][7] += a[i] * b1.w;
            }
        }
        __syncthreads();
    }

    // epilogue: bias (+ relu), store
    float bias[8];
#pragma unroll
    for (int c = 0; c < 8; c++) bias[c] = bl[j0 + c];

#pragma unroll
    for (int i = 0; i < 4; i++) {
        int n = node0 + n0 + i;
        if (n >= N_NODES) continue;
        float v[8];
#pragma unroll
        for (int c = 0; c < 8; c++) {
            float t = acc[i][c] + bias[c];
            if (RELU) t = fmaxf(t, 0.f);
            v[c] = t;
        }
        float4 o0 = make_float4(v[0], v[1], v[2], v[3]);
        float4 o1 = make_float4(v[4], v[5], v[6], v[7]);
        float* dst = xnext + (long long)n * D + j0;
        *(float4*)(dst)     = o0;
        *(float4*)(dst + 4) = o1;
    }
}

// ---------------- column-wise min reduction ---------------------------------
__global__ void k_minreduce(const float* __restrict__ xf) {
    int j = threadIdx.x;                 // 0..127
    float m = 3.4e38f;
    for (int n = blockIdx.x; n < N_NODES; n += gridDim.x)
        m = fminf(m, xf[(long long)n * D + j]);
    atomicMin(&g_minbuf[j], f2mono(m));
}

__global__ void k_writeout(float* __restrict__ out) {
    int j = threadIdx.x;
    out[j] = mono2f(g_minbuf[j]);
}

// ---------------- launch ----------------------------------------------------
extern "C" void kernel_launch(void* const* d_in, const int* in_sizes, int n_in,
                              void* d_out, int out_size) {
    const float* x  = (const float*)d_in[0];
    const int*   ei = (const int*)d_in[1];       // int32! JAX default (no x64)
    const float* Wl = (const float*)d_in[2];     // [L,D,D]
    const float* bl = (const float*)d_in[3];     // [L,D]
    const float* Wr = (const float*)d_in[4];     // [L,D,D]
    float*       out = (float*)d_out;

    // counts + init (once; reused across layers)
    k_init<<<(N_NODES + 255) / 256, 256>>>();
    k_count<<<(N_EDGES + 255) / 256, 256>>>(ei);
    k_inv<<<(N_NODES + 255) / 256, 256>>>();

    float* bufs[2];
    cudaGetSymbolAddress((void**)&bufs[0], g_buf0);
    cudaGetSymbolAddress((void**)&bufs[1], g_buf1);

    const int gemmBlocks   = (N_NODES + BM - 1) / BM;           // 1563
    const int zeroBlocks   = (N_NODES * D / 4 + 255) / 256;     // 12500
    const long long scatterThreads = (long long)N_EDGES * 32;
    const int scatterBlocks = (int)((scatterThreads + 255) / 256);

    const float* cur = x;
    for (int layer = 0; layer < L; layer++) {
        float* nxt = bufs[layer & 1];
        k_zero_agg<<<zeroBlocks, 256>>>();
        k_scatter<<<scatterBlocks, 256>>>(ei, cur);
        const float* wl = Wl + (long long)layer * D * D;
        const float* wr = Wr + (long long)layer * D * D;
        const float* b  = bl + (long long)layer * D;
        if (layer < L - 1)
            k_gemm<1><<<gemmBlocks, 256>>>(cur, wl, b, wr, nxt);
        else
            k_gemm<0><<<gemmBlocks, 256>>>(cur, wl, b, wr, nxt);
        cur = nxt;
    }

    k_minreduce<<<512, D>>>(cur);
    k_writeout<<<1, D>>>(out);
}

// round 3
// speedup vs baseline: 2.5478x; 2.5478x over previous
#include <cuda_runtime.h>
#include <cstdint>

#define N_NODES 100000
#define N_EDGES 1600000
#define D 128
#define L 3

// ---------------- scratch (device globals; no allocation allowed) ----------
__device__ __align__(16) float g_agg [N_NODES * D];   // mean-aggregated features
__device__ __align__(16) float g_buf0[N_NODES * D];   // ping-pong feature buffers
__device__ __align__(16) float g_buf1[N_NODES * D];
__device__ float    g_inv [N_NODES];       // 1 / max(count,1)
__device__ int      g_cnt [N_NODES];
__device__ int      g_off [N_NODES + 1];   // CSR offsets (by dst)
__device__ int      g_cur [N_NODES];       // fill cursors
__device__ int      g_adj [N_EDGES];       // CSR adjacency: src lists per dst
__device__ unsigned g_minbuf[D];           // monotone-uint min accumulator

// monotone mapping: order-preserving float -> uint
__device__ __forceinline__ unsigned f2mono(float f) {
    unsigned u = __float_as_uint(f);
    return (u & 0x80000000u) ? ~u : (u | 0x80000000u);
}
__device__ __forceinline__ float mono2f(unsigned m) {
    return (m & 0x80000000u) ? __uint_as_float(m ^ 0x80000000u)
                             : __uint_as_float(~m);
}

__device__ __forceinline__ uint32_t f2tf32(float f) {
    uint32_t u;
    asm("cvt.rna.tf32.f32 %0, %1;" : "=r"(u) : "f"(f));
    return u;
}

// ---------------- init: zero counts + reset min buffer ---------------------
__global__ void k_init(void) {
    int i = blockIdx.x * blockDim.x + threadIdx.x;
    if (i < N_NODES) g_cnt[i] = 0;
    if (i < D)       g_minbuf[i] = 0xFFFFFFFFu;
}

// ---------------- degree histogram -----------------------------------------
__global__ void k_count(const int* __restrict__ ei) {
    int e = blockIdx.x * blockDim.x + threadIdx.x;
    if (e >= N_EDGES) return;
    atomicAdd(&g_cnt[ei[N_EDGES + e]], 1);
}

// ---------------- single-block exclusive scan -> offsets --------------------
__global__ void __launch_bounds__(1024) k_scan(void) {
    __shared__ int ssum[1024];
    const int CH = (N_NODES + 1023) / 1024;   // 98
    int tid  = threadIdx.x;
    int base = tid * CH;
    int s = 0;
    for (int i = 0; i < CH; i++) {
        int idx = base + i;
        if (idx < N_NODES) s += g_cnt[idx];
    }
    ssum[tid] = s;
    __syncthreads();
    // inclusive Hillis-Steele scan
    for (int off = 1; off < 1024; off <<= 1) {
        int v = (tid >= off) ? ssum[tid - off] : 0;
        __syncthreads();
        ssum[tid] += v;
        __syncthreads();
    }
    int run = (tid > 0) ? ssum[tid - 1] : 0;  // exclusive prefix of chunk
    for (int i = 0; i < CH; i++) {
        int idx = base + i;
        if (idx < N_NODES) {
            g_off[idx] = run;
            run += g_cnt[idx];
        }
    }
    if (tid == 1023) g_off[N_NODES] = ssum[1023];
}

// ---------------- cursor copy + inverse count -------------------------------
__global__ void k_prep(void) {
    int i = blockIdx.x * blockDim.x + threadIdx.x;
    if (i >= N_NODES) return;
    g_cur[i] = g_off[i];
    g_inv[i] = 1.0f / fmaxf((float)g_cnt[i], 1.0f);
}

// ---------------- CSR fill ---------------------------------------------------
__global__ void k_fill(const int* __restrict__ ei) {
    int e = blockIdx.x * blockDim.x + threadIdx.x;
    if (e >= N_EDGES) return;
    int src = ei[e];
    int dst = ei[N_EDGES + e];
    int pos = atomicAdd(&g_cur[dst], 1);
    g_adj[pos] = src;
}

// ---------------- per-layer mean gather: one warp per node ------------------
__global__ void __launch_bounds__(256) k_gather(const float* __restrict__ xcur) {
    int wid  = (blockIdx.x * blockDim.x + threadIdx.x) >> 5;
    int lane = threadIdx.x & 31;
    if (wid >= N_NODES) return;
    int node = wid;

    int off0 = g_off[node];
    int off1 = g_off[node + 1];

    float4 acc = make_float4(0.f, 0.f, 0.f, 0.f);
    int i = off0;
    // unroll-by-4 with independent loads for MLP
    for (; i + 4 <= off1; i += 4) {
        int nb0 = g_adj[i + 0];
        int nb1 = g_adj[i + 1];
        int nb2 = g_adj[i + 2];
        int nb3 = g_adj[i + 3];
        float4 v0 = ((const float4*)(xcur + (long long)nb0 * D))[lane];
        float4 v1 = ((const float4*)(xcur + (long long)nb1 * D))[lane];
        float4 v2 = ((const float4*)(xcur + (long long)nb2 * D))[lane];
        float4 v3 = ((const float4*)(xcur + (long long)nb3 * D))[lane];
        acc.x += v0.x + v1.x + v2.x + v3.x;
        acc.y += v0.y + v1.y + v2.y + v3.y;
        acc.z += v0.z + v1.z + v2.z + v3.z;
        acc.w += v0.w + v1.w + v2.w + v3.w;
    }
    for (; i < off1; i++) {
        int nb = g_adj[i];
        float4 v = ((const float4*)(xcur + (long long)nb * D))[lane];
        acc.x += v.x; acc.y += v.y; acc.z += v.z; acc.w += v.w;
    }
    float s = g_inv[node];
    acc.x *= s; acc.y *= s; acc.z *= s; acc.w *= s;
    ((float4*)(g_agg + (long long)node * D))[lane] = acc;
}

// ---------------- tf32 tensor-core fused SAGE GEMM --------------------------
// out[n,j] = sum_k mean[n,k]*Wl[j,k] + sum_k x[n,k]*Wr[j,k] + bl[j]
// A[N,256] = [mean | x], B = [Wl | Wr] (B col-major k x n since W is [j][k]).
// Block: 128 nodes x 128 cols, BK=32, 256 threads = 8 warps (4m x 2n),
// warp tile 32x64: 2 m16-tiles x 8 n8-tiles of mma.m16n8k8.tf32.
// smem layout k-permuted within 8-groups: k -> 2*(k&3) + ((k>>2)&1), so each
// fragment pair (c, c+4) is a contiguous LDS.64.
#define AS 36            // padded row stride (floats) for A and B smem tiles

__device__ __forceinline__ void mma_tf32(float* d, const uint32_t* a,
                                         uint32_t b0, uint32_t b1) {
    asm volatile(
        "mma.sync.aligned.m16n8k8.row.col.f32.tf32.tf32.f32 "
        "{%0,%1,%2,%3}, {%4,%5,%6,%7}, {%8,%9}, {%0,%1,%2,%3};"
        : "+f"(d[0]), "+f"(d[1]), "+f"(d[2]), "+f"(d[3])
        : "r"(a[0]), "r"(a[1]), "r"(a[2]), "r"(a[3]), "r"(b0), "r"(b1));
}

template<int RELU>
__global__ void __launch_bounds__(256)
k_gemm(const float* __restrict__ xcur,
       const float* __restrict__ Wl,
       const float* __restrict__ bl,
       const float* __restrict__ Wr,
       float* __restrict__ xnext) {
    __shared__ uint32_t As[128 * AS];
    __shared__ uint32_t Bs[128 * AS];

    int tid    = threadIdx.x;
    int wid    = tid >> 5;
    int lane   = tid & 31;
    int g      = lane >> 2;      // group id 0..7
    int c      = lane & 3;       // thread-in-group 0..3
    int warp_m = wid & 3;        // 0..3  -> rows warp_m*32
    int warp_n = wid >> 2;       // 0..1  -> cols warp_n*64
    int blockRow = blockIdx.x * 128;

    float acc[2][8][4];
#pragma unroll
    for (int mt = 0; mt < 2; mt++)
#pragma unroll
        for (int nt = 0; nt < 8; nt++)
#pragma unroll
            for (int r = 0; r < 4; r++) acc[mt][nt][r] = 0.f;

    for (int kc = 0; kc < 8; kc++) {          // 8 chunks of 32 over K=256
        bool meanRegion = (kc < 4);
        int  kb = meanRegion ? kc * 32 : (kc - 4) * 32;
        const float* Asrc = meanRegion ? g_agg : xcur;
        const float* Wsrc = meanRegion ? Wl : Wr;

        // ---- load A tile: 128 rows x 32 k = 1024 float4, 4 per thread
#pragma unroll
        for (int t = 0; t < 4; t++) {
            int idx = tid + t * 256;
            int r   = idx >> 3;               // 0..127
            int k4  = (idx & 7) * 4;          // 0,4,...,28
            int n   = blockRow + r;
            if (n >= N_NODES) n = N_NODES - 1;
            float4 v = *(const float4*)(Asrc + (long long)n * D + kb + k4);
            int kg  = k4 >> 3;
            int odd = (k4 & 4) ? 1 : 0;
            uint32_t* dst = &As[r * AS + kg * 8 + odd];
            dst[0] = f2tf32(v.x);
            dst[2] = f2tf32(v.y);
            dst[4] = f2tf32(v.z);
            dst[6] = f2tf32(v.w);
        }
        // ---- load B tile: 128 cols x 32 k
#pragma unroll
        for (int t = 0; t < 4; t++) {
            int idx = tid + t * 256;
            int j   = idx >> 3;
            int k4  = (idx & 7) * 4;
            float4 v = *(const float4*)(Wsrc + j * D + kb + k4);
            int kg  = k4 >> 3;
            int odd = (k4 & 4) ? 1 : 0;
            uint32_t* dst = &Bs[j * AS + kg * 8 + odd];
            dst[0] = f2tf32(v.x);
            dst[2] = f2tf32(v.y);
            dst[4] = f2tf32(v.z);
            dst[6] = f2tf32(v.w);
        }
        __syncthreads();

#pragma unroll
        for (int ks = 0; ks < 4; ks++) {      // 4 k8-steps per chunk
            uint32_t a[2][4];
#pragma unroll
            for (int mt = 0; mt < 2; mt++) {
                int row = warp_m * 32 + mt * 16 + g;
                uint2 lo = *(uint2*)&As[row * AS + ks * 8 + 2 * c];
                uint2 hi = *(uint2*)&As[(row + 8) * AS + ks * 8 + 2 * c];
                a[mt][0] = lo.x; a[mt][2] = lo.y;
                a[mt][1] = hi.x; a[mt][3] = hi.y;
            }
#pragma unroll
            for (int nt = 0; nt < 8; nt++) {
                int col = warp_n * 64 + nt * 8 + g;
                uint2 b = *(uint2*)&Bs[col * AS + ks * 8 + 2 * c];
                mma_tf32(acc[0][nt], a[0], b.x, b.y);
                mma_tf32(acc[1][nt], a[1], b.x, b.y);
            }
        }
        __syncthreads();
    }

    // ---- epilogue: bias (+relu), store as float2 pairs
#pragma unroll
    for (int nt = 0; nt < 8; nt++) {
        int col = warp_n * 64 + nt * 8 + 2 * c;
        float b0 = bl[col];
        float b1 = bl[col + 1];
#pragma unroll
        for (int mt = 0; mt < 2; mt++) {
            int row0 = blockRow + warp_m * 32 + mt * 16 + g;
            float v0 = acc[mt][nt][0] + b0;
            float v1 = acc[mt][nt][1] + b1;
            float v2 = acc[mt][nt][2] + b0;
            float v3 = acc[mt][nt][3] + b1;
            if (RELU) {
                v0 = fmaxf(v0, 0.f); v1 = fmaxf(v1, 0.f);
                v2 = fmaxf(v2, 0.f); v3 = fmaxf(v3, 0.f);
            }
            if (row0 < N_NODES)
                *(float2*)(xnext + (long long)row0 * D + col) = make_float2(v0, v1);
            if (row0 + 8 < N_NODES)
                *(float2*)(xnext + (long long)(row0 + 8) * D + col) = make_float2(v2, v3);
        }
    }
}

// ---------------- column-wise min reduction ---------------------------------
__global__ void k_minreduce(const float* __restrict__ xf) {
    int j = threadIdx.x;                 // 0..127
    float m = 3.4e38f;
    for (int n = blockIdx.x; n < N_NODES; n += gridDim.x)
        m = fminf(m, xf[(long long)n * D + j]);
    atomicMin(&g_minbuf[j], f2mono(m));
}

__global__ void k_writeout(float* __restrict__ out) {
    int j = threadIdx.x;
    out[j] = mono2f(g_minbuf[j]);
}

// ---------------- launch ----------------------------------------------------
extern "C" void kernel_launch(void* const* d_in, const int* in_sizes, int n_in,
                              void* d_out, int out_size) {
    const float* x  = (const float*)d_in[0];
    const int*   ei = (const int*)d_in[1];       // int32 edge index
    const float* Wl = (const float*)d_in[2];     // [L,D,D]
    const float* bl = (const float*)d_in[3];     // [L,D]
    const float* Wr = (const float*)d_in[4];     // [L,D,D]
    float*       out = (float*)d_out;

    // ---- CSR build (once per launch)
    k_init <<<(N_NODES + 255) / 256, 256>>>();
    k_count<<<(N_EDGES + 255) / 256, 256>>>(ei);
    k_scan <<<1, 1024>>>();
    k_prep <<<(N_NODES + 255) / 256, 256>>>();
    k_fill <<<(N_EDGES + 255) / 256, 256>>>(ei);

    float* bufs[2];
    cudaGetSymbolAddress((void**)&bufs[0], g_buf0);
    cudaGetSymbolAddress((void**)&bufs[1], g_buf1);

    const int gemmBlocks   = (N_NODES + 127) / 128;        // 782
    const int gatherBlocks = (N_NODES + 7) / 8;            // 12500 (8 warps/block)

    const float* cur = x;
    for (int layer = 0; layer < L; layer++) {
        float* nxt = bufs[layer & 1];
        k_gather<<<gatherBlocks, 256>>>(cur);
        const float* wl = Wl + (long long)layer * D * D;
        const float* wr = Wr + (long long)layer * D * D;
        const float* b  = bl + (long long)layer * D;
        if (layer < L - 1)
            k_gemm<1><<<gemmBlocks, 256>>>(cur, wl, b, wr, nxt);
        else
            k_gemm<0><<<gemmBlocks, 256>>>(cur, wl, b, wr, nxt);
        cur = nxt;
    }

    k_minreduce<<<512, D>>>(cur);
    k_writeout<<<1, D>>>(out);
}